// round 11
// baseline (speedup 1.0000x reference)
#include <cuda_runtime.h>

#define Nn 768
#define Hh 32
#define Ee 24576
#define Pp 4096
#define NW 24              // 768/32 bitmask words per row
#define STR 96             // fixed CSR stride per row
#define WBUD 512           // per-(row,window) pair budget
#define NAGG 384

// ---------------- scratch ----------------
__device__ unsigned d_abits[Nn*NW];     // zeroed by k_z after last read
__device__ unsigned d_nbits[Nn*NW];     // zeroed by k_z after last read
__device__ unsigned char d_maskb[Nn*Nn];
__device__ float d_dinv[Nn];
__device__ float d_h [Nn*Hh];
__device__ float d_hT[Nn*Hh];
__device__ float d_hP[Nn*Hh];
__device__ int   d_cnt [Nn];            // zeroed by k_z
__device__ int   d_col[Nn*STR];
__device__ int   d_wcnt[Nn*NW];         // per-(row,window) pair counts (overwritten each run)
__device__ int   d_pairw[Nn*NW*WBUD];   // f | e_local<<17 | j_local<<24, bucketed by window
__device__ float d_xe [Nn*STR*Hh];
__device__ float d_mul[Nn*STR*Hh];
__device__ float d_z  [(size_t)Nn*Nn*Hh];
__device__ float d_p1[NAGG*Hh], d_p2[NAGG*Hh];
__device__ float d_S1[Hh], d_S2[Hh];    // zeroed by k_sf
__device__ int   d_cntM;                // zeroed by k_sf

// ---------------- f32x2 helpers ----------------
__device__ __forceinline__ void fma2(unsigned long long& d, unsigned long long a, unsigned long long b){
    asm("fma.rn.f32x2 %0, %1, %2, %0;" : "+l"(d) : "l"(a), "l"(b));
}
__device__ __forceinline__ unsigned long long pk2(float lo, float hi){
    unsigned long long r; asm("mov.b64 %0,{%1,%2};" : "=l"(r) : "f"(lo), "f"(hi)); return r;
}
__device__ __forceinline__ float upk_sum(unsigned long long v){
    float lo, hi; asm("mov.b64 {%0,%1},%2;" : "=f"(lo), "=f"(hi) : "l"(v)); return lo+hi;
}

// ================= setup: scatter bits + fixed-stride CSR + zero stats =================
__global__ void k_sf(const int* __restrict__ ei, const int* __restrict__ pos) {
    int t = blockIdx.x*256 + threadIdx.x;
    if (t < Hh){ d_S1[t]=0.f; d_S2[t]=0.f; }
    if (t == Hh) d_cntM = 0;
    int u = ei[t], v = ei[Ee+t];
    atomicOr(&d_abits[u*NW+(v>>5)], 1u<<(v&31));
    int slot = atomicAdd(&d_cnt[u], 1);
    d_col[u*STR+slot] = v;
    if (t < Pp){
        int a=pos[2*t], b=pos[2*t+1];
        atomicOr(&d_nbits[a*NW+(b>>5)], 1u<<(b&31));
        atomicOr(&d_nbits[b*NW+(a>>5)], 1u<<(a&31));
    }
}

// ================= per-row pair build: SINGLE pass, window buckets =================
__global__ void __launch_bounds__(256) k_build() {
    __shared__ int wc[NW];
    int tid = threadIdx.x, w = tid>>5, lane = tid&31;
    int i = blockIdx.x;
    if (tid < NW) wc[tid]=0;
    __syncthreads();
    int es = i*STR, deg = d_cnt[i];
    int* prow = d_pairw + i*NW*WBUD;
    for (int e=w; e<deg; e+=8){
        int k = d_col[es+e];
        int fk = k*STR, dk = d_cnt[k];
        for (int f=lane; f<dk; f+=32){
            int j = d_col[fk+f];
            int win = j>>5;
            int slot = atomicAdd(&wc[win], 1);
            if (slot < WBUD)
                prow[win*WBUD + slot] = (fk+f) | (e<<17) | ((j&31)<<24);
        }
    }
    __syncthreads();
    if (tid < NW) d_wcnt[i*NW+tid] = min(wc[tid], WBUD);
}

// ================= GCN =================
// embed + dinv + hT = dinv * (emb[x] @ W0)
__global__ void k_hw0(const int* __restrict__ x, const float* __restrict__ emb,
                      const float* __restrict__ gcnW) {
    int w = threadIdx.x>>5, lane = threadIdx.x&31;
    int r = blockIdx.x*8 + w;
    int s = (lane<NW) ? __popc(d_abits[r*NW+lane]) : 0;
    #pragma unroll
    for (int o=16;o;o>>=1) s += __shfl_xor_sync(0xffffffffu, s, o);
    float dv = rsqrtf((float)s + 1.0f);
    if (lane==0) d_dinv[r] = dv;
    float hv = emb[x[r]*Hh+lane];
    float acc = 0.f;
    #pragma unroll
    for (int k=0;k<32;k++) acc += __shfl_sync(0xffffffffu,hv,k) * gcnW[k*Hh+lane];
    d_hT[r*Hh+lane] = dv*acc;
}

// agg: 384 blocks, 2 rows/block, warp = quarter-row (6 words)
template<int L>
__global__ void k_agg(const float* __restrict__ gcnb) {
    __shared__ float sAg[8][32];
    __shared__ float red1[2][32], red2[2][32];
    int w = threadIdx.x>>5, lane = threadIdx.x&31;
    int r = blockIdx.x*2 + (w>>2);
    int quarter = w&3;
    float aggv = 0.f;
    #pragma unroll 1
    for (int wd=quarter*6; wd<quarter*6+6; wd++){
        unsigned m = d_abits[r*NW+wd];
        int jb = wd*32;
        while (m){ int b=__ffs(m)-1; m&=m-1; aggv += d_hT[(jb+b)*Hh+lane]; }
    }
    sAg[w][lane]=aggv;
    __syncthreads();
    if (quarter==0){
        float tot = sAg[w][lane]+sAg[w+1][lane]+sAg[w+2][lane]+sAg[w+3][lane];
        float v = d_dinv[r]*(tot + d_hT[r*Hh+lane]) + gcnb[L*Hh+lane];
        d_hP[r*Hh+lane]=v;
        red1[w>>2][lane]=v; red2[w>>2][lane]=v*v;
    }
    __syncthreads();
    if (w==0){
        float s1=red1[0][lane]+red1[1][lane];
        float s2=red2[0][lane]+red2[1][lane];
        d_p1[blockIdx.x*32+lane]=s1; d_p2[blockIdx.x*32+lane]=s2;
    }
}

__global__ void k_hw1(const float* __restrict__ gcnW) {
    int w = threadIdx.x>>5, lane = threadIdx.x&31;
    int r = blockIdx.x*8 + w;
    float s1=0.f, s2=0.f;
    #pragma unroll 4
    for (int b=0;b<NAGG;b++){ s1+=d_p1[b*32+lane]; s2+=d_p2[b*32+lane]; }
    float mean = s1/(float)Nn;
    float inv  = rsqrtf(s2/(float)Nn - mean*mean + 1e-5f);
    float hv = fmaxf((d_hP[r*Hh+lane]-mean)*inv, 0.f);
    float acc = 0.f;
    #pragma unroll
    for (int k=0;k<32;k++) acc += __shfl_sync(0xffffffffu,hv,k) * gcnW[Hh*Hh + k*Hh+lane];
    d_hT[r*Hh+lane] = d_dinv[r]*acc;
}

__global__ void k_norm1() {
    int w = threadIdx.x>>5, lane = threadIdx.x&31;
    int r = blockIdx.x*8 + w;
    float s1=0.f, s2=0.f;
    #pragma unroll 4
    for (int b=0;b<NAGG;b++){ s1+=d_p1[b*32+lane]; s2+=d_p2[b*32+lane]; }
    float mean = s1/(float)Nn;
    float inv  = rsqrtf(s2/(float)Nn - mean*mean + 1e-5f);
    d_h[r*Hh+lane] = fmaxf((d_hP[r*Hh+lane]-mean)*inv, 0.f);
}

// ================= edge MLPs: 4 edges per warp =================
__global__ void k_mlp(const float* __restrict__ W1, const float* __restrict__ b1,
                      const float* __restrict__ W2, const float* __restrict__ b2) {
    int w = threadIdx.x>>5, lane = threadIdx.x&31;
    int wid = blockIdx.x*8 + w;
    int s0 = wid*4;
    int u = s0/STR, idx0 = s0 - u*STR;
    int deg = d_cnt[u];
    if (idx0 >= deg) return;
    int nv = min(deg - idx0, 4);
    float hu = d_h[u*Hh+lane];
    float hv[4], x1[4], x2[4];
    #pragma unroll
    for (int q=0;q<4;q++){
        int v = (q<nv) ? d_col[s0+q] : d_col[s0];
        hv[q] = d_h[v*Hh+lane];
        x1[q] = b1[lane]; x2[q] = b2[lane];
    }
    #pragma unroll 4
    for (int k=0;k<32;k++){
        float w1a=W1[k*Hh+lane], w1b=W1[(k+32)*Hh+lane];
        float w2a=W2[k*Hh+lane], w2b=W2[(k+32)*Hh+lane];
        float a = __shfl_sync(0xffffffffu,hu,k);
        #pragma unroll
        for (int q=0;q<4;q++){
            float b = __shfl_sync(0xffffffffu,hv[q],k);
            x1[q] += a*w1a + b*w1b;
            x2[q] += a*w2a + b*w2b;
        }
    }
    #pragma unroll
    for (int q=0;q<4;q++){
        if (q<nv){
            d_xe [(s0+q)*Hh+lane]=fmaxf(x1[q],0.f);
            d_mul[(s0+q)*Hh+lane]=fmaxf(x2[q],0.f);
        }
    }
}

// ================= hot kernel: block = row; window buckets; deep value pipeline =================
__global__ void __launch_bounds__(256,4) k_z(const float* __restrict__ W3,
                                             const float* __restrict__ b3v) {
    __shared__ unsigned long long sW[512];
    __shared__ float sxe[STR*Hh];
    __shared__ float sC[8][1024];
    __shared__ float sr1[8][32], sr2[8][32];
    __shared__ int src[8];
    int tid = threadIdx.x, w = tid>>5, lane = tid&31;
    int i = blockIdx.x;

    #pragma unroll
    for (int f=tid; f<512; f+=256){
        int t = f>>5, ln = f&31;
        sW[f] = pk2(W3[(2*t)*Hh+ln], W3[(2*t+1)*Hh+ln]);
    }
    int deg = d_cnt[i];
    {
        const float4* src4 = (const float4*)(d_xe + i*STR*Hh);
        float4* dst4 = (float4*)sxe;
        for (int t=tid; t<deg*8; t+=256) dst4[t]=src4[t];
    }
    __syncthreads();

    float w3last = W3[32*Hh+lane];
    float bb = b3v[lane];
    float s1=0.f, s2=0.f; int c0=0;
    float* sCw = sC[w];

    #pragma unroll 1
    for (int win=w; win<NW; win+=8){
        int ij0 = i*Nn + win*32;
        int n = d_wcnt[i*NW+win];
        unsigned mA = d_abits[i*NW + win];
        unsigned mN = d_nbits[i*NW + win];
        if (lane==0){ d_abits[i*NW+win]=0u; d_nbits[i*NW+win]=0u; }  // reset for replay
        unsigned tb = 0;

        if (n | mA){
            {
                float4 z4 = make_float4(0.f,0.f,0.f,0.f);
                float4* p4 = (float4*)sCw;
                #pragma unroll
                for (int t=lane; t<256; t+=32) p4[t]=z4;
            }
            __syncwarp();

            // ---- phase A: window pair stream; 3-stage desc, 2-stage value pipeline ----
            const int* pw = d_pairw + (i*NW+win)*WBUD;
            int t = 0;
            if (n >= 12){
                int d0[4], d1[4], d2[4]; float m0[4], m1[4];
                #pragma unroll
                for (int q=0;q<4;q++) d0[q]=pw[q];
                #pragma unroll
                for (int q=0;q<4;q++) d1[q]=pw[4+q];
                #pragma unroll
                for (int q=0;q<4;q++) d2[q]=pw[8+q];
                #pragma unroll
                for (int q=0;q<4;q++) m0[q]=d_mul[(d0[q]&0x1FFFF)*Hh+lane];
                #pragma unroll
                for (int q=0;q<4;q++) m1[q]=d_mul[(d1[q]&0x1FFFF)*Hh+lane];
                t = 12;
                while (t+4 <= n){
                    int d3[4];
                    #pragma unroll
                    for (int q=0;q<4;q++) d3[q]=pw[t+q];
                    float m2[4];
                    #pragma unroll
                    for (int q=0;q<4;q++) m2[q]=d_mul[(d2[q]&0x1FFFF)*Hh+lane];
                    #pragma unroll
                    for (int q=0;q<4;q++){
                        sCw[(d0[q]>>24)*Hh+lane] += sxe[((d0[q]>>17)&127)*Hh+lane]*m0[q];
                        tb |= 1u<<(d0[q]>>24);
                    }
                    #pragma unroll
                    for (int q=0;q<4;q++){ d0[q]=d1[q]; m0[q]=m1[q]; d1[q]=d2[q]; m1[q]=m2[q]; d2[q]=d3[q]; }
                    t += 4;
                }
                float m2[4];
                #pragma unroll
                for (int q=0;q<4;q++) m2[q]=d_mul[(d2[q]&0x1FFFF)*Hh+lane];
                #pragma unroll
                for (int q=0;q<4;q++){
                    sCw[(d0[q]>>24)*Hh+lane] += sxe[((d0[q]>>17)&127)*Hh+lane]*m0[q];
                    tb |= 1u<<(d0[q]>>24);
                }
                #pragma unroll
                for (int q=0;q<4;q++){
                    sCw[(d1[q]>>24)*Hh+lane] += sxe[((d1[q]>>17)&127)*Hh+lane]*m1[q];
                    tb |= 1u<<(d1[q]>>24);
                }
                #pragma unroll
                for (int q=0;q<4;q++){
                    sCw[(d2[q]>>24)*Hh+lane] += sxe[((d2[q]>>17)&127)*Hh+lane]*m2[q];
                    tb |= 1u<<(d2[q]>>24);
                }
            }
            for (; t<n; t++){
                int p = pw[t];
                sCw[(p>>24)*Hh+lane] += sxe[((p>>17)&127)*Hh+lane]*d_mul[(p&0x1FFFF)*Hh+lane];
                tb |= 1u<<(p>>24);
            }
            __syncwarp();
        }

        unsigned mM = mA | tb;
        d_maskb[ij0+lane] = (unsigned char)((mM>>lane)&1u);
        c0 += __popc(mM);

        // ---- phase B ----
        unsigned rem = mM;
        while (rem){
            int b = __ffs(rem)-1; rem &= rem-1;
            const ulonglong2* Cj = (const ulonglong2*)(sCw + b*Hh);
            unsigned long long a0=0ull, a1=0ull;
            #pragma unroll
            for (int q=0;q<4;q++){
                ulonglong2 cA = Cj[q];
                ulonglong2 cB = Cj[q+4];
                fma2(a0, cA.x, sW[(2*q)*32+lane]);     fma2(a0, cA.y, sW[(2*q+1)*32+lane]);
                fma2(a1, cB.x, sW[(2*q+8)*32+lane]);   fma2(a1, cB.y, sW[(2*q+9)*32+lane]);
            }
            float acc = bb + upk_sum(a0) + upk_sum(a1) + (((mA>>b)&1u) ? w3last : 0.f);
            s1 += acc; s2 += acc*acc;
            if ((mN>>b)&1u) d_z[(size_t)(ij0+b)*Hh + lane] = acc;
        }
    }
    sr1[w][lane]=s1; sr2[w][lane]=s2; if (lane==0) src[w]=c0;
    __syncthreads();
    if (w==0){
        float a=0.f, b=0.f;
        #pragma unroll
        for (int r=0;r<8;r++){ a+=sr1[r][lane]; b+=sr2[r][lane]; }
        atomicAdd(&d_S1[lane], a);
        atomicAdd(&d_S2[lane], b);
        if (lane==0){ int cc=0; for (int r=0;r<8;r++) cc+=src[r]; atomicAdd(&d_cntM, cc); }
    }
    if (tid==0) d_cnt[i]=0;                    // reset for replay
}

// ================= output =================
__global__ void k_pos(const int* __restrict__ pos, const float* __restrict__ linW,
                      const float* __restrict__ linb, float* __restrict__ out) {
    int w = threadIdx.x>>5, lane = threadIdx.x&31;
    int p = blockIdx.x*8 + w;
    float cnt = (float)d_cntM;
    float mean = d_S1[lane]/cnt;
    float inv  = rsqrtf(d_S2[lane]/cnt - mean*mean + 1e-5f);
    int p0 = pos[2*p], p1 = pos[2*p+1];
    float acc = d_h[p0*Hh+lane]*d_h[p1*Hh+lane]*linW[Hh+lane];
    if (d_maskb[p0*Nn+p1]) {
        float z1 = d_z[((size_t)p0*Nn+p1)*Hh+lane];
        float z2 = d_z[((size_t)p1*Nn+p0)*Hh+lane];
        acc += fmaxf((z1-mean)*inv,0.f)*fmaxf((z2-mean)*inv,0.f)*linW[lane];
    }
    for (int o=16;o;o>>=1) acc += __shfl_down_sync(0xffffffffu, acc, o);
    if (lane==0) out[p] = acc + linb[0];
}

// ================= launch =================
extern "C" void kernel_launch(void* const* d_in, const int* in_sizes, int n_in,
                              void* d_out, int out_size) {
    const int*   x    = (const int*)  d_in[0];
    const int*   ei   = (const int*)  d_in[1];
    const int*   pos  = (const int*)  d_in[2];
    const float* emb  = (const float*)d_in[3];
    const float* gcnW = (const float*)d_in[4];
    const float* gcnb = (const float*)d_in[5];
    const float* W1   = (const float*)d_in[6];
    const float* b1   = (const float*)d_in[7];
    const float* W2   = (const float*)d_in[8];
    const float* b2   = (const float*)d_in[9];
    const float* W3   = (const float*)d_in[10];
    const float* b3   = (const float*)d_in[11];
    const float* linW = (const float*)d_in[12];
    const float* linb = (const float*)d_in[13];
    float* out = (float*)d_out;

    k_sf     <<<96, 256>>>(ei, pos);
    k_build  <<<Nn, 256>>>();
    k_hw0    <<<96, 256>>>(x, emb, gcnW);
    k_agg<0> <<<NAGG,256>>>(gcnb);      // 384 blocks × 2 rows = 768 rows (was the bug)
    k_hw1    <<<96, 256>>>(gcnW);
    k_agg<1> <<<NAGG,256>>>(gcnb);
    k_norm1  <<<96, 256>>>();
    k_mlp    <<<Nn*STR/32,256>>>(W1,b1,W2,b2);
    k_z      <<<Nn, 256>>>(W3,b3);
    k_pos    <<<Pp/8,256>>>(pos, linW, linb, out);
}

// round 12
// speedup vs baseline: 1.2093x; 1.2093x over previous
#include <cuda_runtime.h>

#define Nn 768
#define Hh 32
#define Ee 24576
#define Pp 4096
#define NW 24              // 768/32 bitmask words per row
#define STR 96             // fixed CSR stride per row
#define BUD 6144           // per-row pair budget
#define NAGG 384

// ---------------- scratch ----------------
__device__ unsigned d_abits[Nn*NW];     // zeroed by k_z after last read
__device__ unsigned d_nbits[Nn*NW];     // zeroed by k_z after last read
__device__ unsigned char d_maskb[Nn*Nn];
__device__ float d_dinv[Nn];
__device__ float d_h [Nn*Hh];
__device__ float d_hT[Nn*Hh];
__device__ float d_hP[Nn*Hh];
__device__ int   d_cnt [Nn];            // zeroed by k_z
__device__ int   d_col[Nn*STR];
__device__ int   d_ijstart[Nn*Nn];      // local (within-row) pair-segment starts
__device__ int   d_ijend  [Nn*Nn];
__device__ int   d_pair1[Nn*BUD];       // f_glob | e_local<<17 | j_local<<24
__device__ float d_xe [Nn*STR*Hh];
__device__ float d_mul[Nn*STR*Hh];
__device__ float d_z  [(size_t)Nn*Nn*Hh];
__device__ float d_p1[NAGG*Hh], d_p2[NAGG*Hh];
__device__ float d_S1[Hh], d_S2[Hh];    // zeroed by k_sf
__device__ int   d_cntM;                // zeroed by k_sf

// ---------------- f32x2 helpers ----------------
__device__ __forceinline__ void fma2(unsigned long long& d, unsigned long long a, unsigned long long b){
    asm("fma.rn.f32x2 %0, %1, %2, %0;" : "+l"(d) : "l"(a), "l"(b));
}
__device__ __forceinline__ unsigned long long pk2(float lo, float hi){
    unsigned long long r; asm("mov.b64 %0,{%1,%2};" : "=l"(r) : "f"(lo), "f"(hi)); return r;
}
__device__ __forceinline__ float upk_sum(unsigned long long v){
    float lo, hi; asm("mov.b64 {%0,%1},%2;" : "=f"(lo), "=f"(hi) : "l"(v)); return lo+hi;
}

// ================= setup: scatter bits + fixed-stride CSR + zero stats =================
__global__ void k_sf(const int* __restrict__ ei, const int* __restrict__ pos) {
    int t = blockIdx.x*256 + threadIdx.x;
    if (t < Hh){ d_S1[t]=0.f; d_S2[t]=0.f; }
    if (t == Hh) d_cntM = 0;
    int u = ei[t], v = ei[Ee+t];
    atomicOr(&d_abits[u*NW+(v>>5)], 1u<<(v&31));
    int slot = atomicAdd(&d_cnt[u], 1);
    d_col[u*STR+slot] = v;
    if (t < Pp){
        int a=pos[2*t], b=pos[2*t+1];
        atomicOr(&d_nbits[a*NW+(b>>5)], 1u<<(b&31));
        atomicOr(&d_nbits[b*NW+(a>>5)], 1u<<(a&31));
    }
}

// ================= per-row pair build (768 blocks, two-pass, per-j buckets) =================
__global__ void __launch_bounds__(256) k_build() {
    __shared__ int scnt[Nn];
    __shared__ int scur[Nn];
    __shared__ int wsum[8];
    int tid = threadIdx.x, w = tid>>5, lane = tid&31;
    int i = blockIdx.x;
    for (int t=tid; t<Nn; t+=256) scnt[t]=0;
    __syncthreads();
    int es = i*STR, deg = d_cnt[i];
    for (int e=w; e<deg; e+=8){
        int k = d_col[es+e];
        int fk = k*STR, dk = d_cnt[k];
        for (int f=lane; f<dk; f+=32) atomicAdd(&scnt[d_col[fk+f]], 1);
    }
    __syncthreads();
    int lo = tid*3;
    int c0=scnt[lo], c1=scnt[lo+1], c2=scnt[lo+2];
    int s = c0+c1+c2, sc = s;
    #pragma unroll
    for (int o=1;o<32;o<<=1){ int t2=__shfl_up_sync(0xffffffffu,sc,o); if (lane>=o) sc+=t2; }
    if (lane==31) wsum[w]=sc;
    __syncthreads();
    if (w==0){
        int v = (lane<8) ? wsum[lane] : 0;
        int p = v;
        #pragma unroll
        for (int o=1;o<8;o<<=1){ int t2=__shfl_up_sync(0xffffffffu,p,o); if (lane>=o) p+=t2; }
        if (lane<8) wsum[lane]=p-v;
    }
    __syncthreads();
    int b0 = wsum[w] + sc - s;
    scur[lo]=b0; scur[lo+1]=b0+c0; scur[lo+2]=b0+c0+c1;
    d_ijstart[i*Nn+lo]  =b0;        d_ijend[i*Nn+lo]  =b0+c0;
    d_ijstart[i*Nn+lo+1]=b0+c0;     d_ijend[i*Nn+lo+1]=b0+c0+c1;
    d_ijstart[i*Nn+lo+2]=b0+c0+c1;  d_ijend[i*Nn+lo+2]=b0+c0+c1+c2;
    __syncthreads();
    int* prow = d_pair1 + i*BUD;
    for (int e=w; e<deg; e+=8){
        int k = d_col[es+e];
        int fk = k*STR, dk = d_cnt[k];
        for (int f=lane; f<dk; f+=32){
            int j = d_col[fk+f];
            int slot = atomicAdd(&scur[j], 1);
            prow[slot] = (fk+f) | (e<<17) | ((j&31)<<24);
        }
    }
}

// ================= GCN =================
// embed + dinv + hT = dinv * (emb[x] @ W0)
__global__ void k_hw0(const int* __restrict__ x, const float* __restrict__ emb,
                      const float* __restrict__ gcnW) {
    int w = threadIdx.x>>5, lane = threadIdx.x&31;
    int r = blockIdx.x*8 + w;
    int s = (lane<NW) ? __popc(d_abits[r*NW+lane]) : 0;
    #pragma unroll
    for (int o=16;o;o>>=1) s += __shfl_xor_sync(0xffffffffu, s, o);
    float dv = rsqrtf((float)s + 1.0f);
    if (lane==0) d_dinv[r] = dv;
    float hv = emb[x[r]*Hh+lane];
    float acc = 0.f;
    #pragma unroll
    for (int k=0;k<32;k++) acc += __shfl_sync(0xffffffffu,hv,k) * gcnW[k*Hh+lane];
    d_hT[r*Hh+lane] = dv*acc;
}

// agg: 384 blocks, 2 rows/block, warp = quarter-row (verified faster in R11)
template<int L>
__global__ void k_agg(const float* __restrict__ gcnb) {
    __shared__ float sAg[8][32];
    __shared__ float red1[2][32], red2[2][32];
    int w = threadIdx.x>>5, lane = threadIdx.x&31;
    int r = blockIdx.x*2 + (w>>2);
    int quarter = w&3;
    float aggv = 0.f;
    #pragma unroll 1
    for (int wd=quarter*6; wd<quarter*6+6; wd++){
        unsigned m = d_abits[r*NW+wd];
        int jb = wd*32;
        while (m){ int b=__ffs(m)-1; m&=m-1; aggv += d_hT[(jb+b)*Hh+lane]; }
    }
    sAg[w][lane]=aggv;
    __syncthreads();
    if (quarter==0){
        float tot = sAg[w][lane]+sAg[w+1][lane]+sAg[w+2][lane]+sAg[w+3][lane];
        float v = d_dinv[r]*(tot + d_hT[r*Hh+lane]) + gcnb[L*Hh+lane];
        d_hP[r*Hh+lane]=v;
        red1[w>>2][lane]=v; red2[w>>2][lane]=v*v;
    }
    __syncthreads();
    if (w==0){
        float s1=red1[0][lane]+red1[1][lane];
        float s2=red2[0][lane]+red2[1][lane];
        d_p1[blockIdx.x*32+lane]=s1; d_p2[blockIdx.x*32+lane]=s2;
    }
}

__global__ void k_hw1(const float* __restrict__ gcnW) {
    int w = threadIdx.x>>5, lane = threadIdx.x&31;
    int r = blockIdx.x*8 + w;
    float s1=0.f, s2=0.f;
    #pragma unroll 4
    for (int b=0;b<NAGG;b++){ s1+=d_p1[b*32+lane]; s2+=d_p2[b*32+lane]; }
    float mean = s1/(float)Nn;
    float inv  = rsqrtf(s2/(float)Nn - mean*mean + 1e-5f);
    float hv = fmaxf((d_hP[r*Hh+lane]-mean)*inv, 0.f);
    float acc = 0.f;
    #pragma unroll
    for (int k=0;k<32;k++) acc += __shfl_sync(0xffffffffu,hv,k) * gcnW[Hh*Hh + k*Hh+lane];
    d_hT[r*Hh+lane] = d_dinv[r]*acc;
}

__global__ void k_norm1() {
    int w = threadIdx.x>>5, lane = threadIdx.x&31;
    int r = blockIdx.x*8 + w;
    float s1=0.f, s2=0.f;
    #pragma unroll 4
    for (int b=0;b<NAGG;b++){ s1+=d_p1[b*32+lane]; s2+=d_p2[b*32+lane]; }
    float mean = s1/(float)Nn;
    float inv  = rsqrtf(s2/(float)Nn - mean*mean + 1e-5f);
    d_h[r*Hh+lane] = fmaxf((d_hP[r*Hh+lane]-mean)*inv, 0.f);
}

// ================= edge MLPs: 4 edges per warp =================
__global__ void k_mlp(const float* __restrict__ W1, const float* __restrict__ b1,
                      const float* __restrict__ W2, const float* __restrict__ b2) {
    int w = threadIdx.x>>5, lane = threadIdx.x&31;
    int wid = blockIdx.x*8 + w;
    int s0 = wid*4;
    int u = s0/STR, idx0 = s0 - u*STR;
    int deg = d_cnt[u];
    if (idx0 >= deg) return;
    int nv = min(deg - idx0, 4);
    float hu = d_h[u*Hh+lane];
    float hv[4], x1[4], x2[4];
    #pragma unroll
    for (int q=0;q<4;q++){
        int v = (q<nv) ? d_col[s0+q] : d_col[s0];
        hv[q] = d_h[v*Hh+lane];
        x1[q] = b1[lane]; x2[q] = b2[lane];
    }
    #pragma unroll 4
    for (int k=0;k<32;k++){
        float w1a=W1[k*Hh+lane], w1b=W1[(k+32)*Hh+lane];
        float w2a=W2[k*Hh+lane], w2b=W2[(k+32)*Hh+lane];
        float a = __shfl_sync(0xffffffffu,hu,k);
        #pragma unroll
        for (int q=0;q<4;q++){
            float b = __shfl_sync(0xffffffffu,hv[q],k);
            x1[q] += a*w1a + b*w1b;
            x2[q] += a*w2a + b*w2b;
        }
    }
    #pragma unroll
    for (int q=0;q<4;q++){
        if (q<nv){
            d_xe [(s0+q)*Hh+lane]=fmaxf(x1[q],0.f);
            d_mul[(s0+q)*Hh+lane]=fmaxf(x2[q],0.f);
        }
    }
}

// run-detection accumulate: pairs with equal j are contiguous (per-j build buckets)
#define PROC1(dv, mv) { \
    int jj_ = (dv)>>24; \
    float val_ = sxe[(((dv)>>17)&127)*Hh+lane]*(mv); \
    if (jj_ != jcur){ sCw[jcur*Hh+lane] += accv; accv = 0.f; jcur = jj_; } \
    accv += val_; }

// ================= hot kernel: block = row; xe staged; run-detect register C =================
__global__ void __launch_bounds__(256,4) k_z(const float* __restrict__ W3,
                                             const float* __restrict__ b3v) {
    __shared__ unsigned long long sW[512];
    __shared__ float sxe[STR*Hh];
    __shared__ float sC[8][1024];
    __shared__ float sr1[8][32], sr2[8][32];
    __shared__ int src[8];
    int tid = threadIdx.x, w = tid>>5, lane = tid&31;
    int i = blockIdx.x;

    #pragma unroll
    for (int f=tid; f<512; f+=256){
        int t = f>>5, ln = f&31;
        sW[f] = pk2(W3[(2*t)*Hh+ln], W3[(2*t+1)*Hh+ln]);
    }
    int deg = d_cnt[i];
    {
        const float4* src4 = (const float4*)(d_xe + i*STR*Hh);
        float4* dst4 = (float4*)sxe;
        for (int t=tid; t<deg*8; t+=256) dst4[t]=src4[t];
    }
    __syncthreads();

    float w3last = W3[32*Hh+lane];
    float bb = b3v[lane];
    float s1=0.f, s2=0.f; int c0=0;
    float* sCw = sC[w];
    const int* prow = d_pair1 + i*BUD;

    #pragma unroll 1
    for (int win=w; win<NW; win+=8){
        int ij0 = i*Nn + win*32;
        int start = d_ijstart[ij0+lane];
        int end   = d_ijend  [ij0+lane];
        unsigned mA = d_abits[i*NW + win];
        unsigned mN = d_nbits[i*NW + win];
        unsigned hasP = __ballot_sync(0xffffffffu, end>start);
        unsigned mM = mA | hasP;
        d_maskb[ij0+lane] = (unsigned char)((mM>>lane)&1u);
        c0 += __popc(mM);
        if (lane==0){ d_abits[i*NW+win]=0u; d_nbits[i*NW+win]=0u; }  // reset for replay

        if (mM){
            {
                float4 z4 = make_float4(0.f,0.f,0.f,0.f);
                float4* p4 = (float4*)sCw;
                #pragma unroll
                for (int t=lane; t<256; t+=32) p4[t]=z4;
            }
            __syncwarp();

            // ---- phase A: flat stream; depth-2 value pipeline; register run accumulation ----
            int winS = __shfl_sync(0xffffffffu, start, 0);
            int winE = __shfl_sync(0xffffffffu, end, 31);
            if (winE > winS){
                int jcur = prow[winS]>>24;
                float accv = 0.f;
                int t = winS;
                if (winE - winS >= 8){
                    int d0[4], d1[4]; float m0[4];
                    #pragma unroll
                    for (int q=0;q<4;q++) d0[q]=prow[t+q];
                    #pragma unroll
                    for (int q=0;q<4;q++) d1[q]=prow[t+4+q];
                    #pragma unroll
                    for (int q=0;q<4;q++) m0[q]=d_mul[(d0[q]&0x1FFFF)*Hh+lane];
                    t += 8;
                    while (t+4 <= winE){
                        int d2[4];
                        #pragma unroll
                        for (int q=0;q<4;q++) d2[q]=prow[t+q];
                        float m1[4];
                        #pragma unroll
                        for (int q=0;q<4;q++) m1[q]=d_mul[(d1[q]&0x1FFFF)*Hh+lane];
                        #pragma unroll
                        for (int q=0;q<4;q++) PROC1(d0[q], m0[q]);
                        #pragma unroll
                        for (int q=0;q<4;q++){ d0[q]=d1[q]; m0[q]=m1[q]; d1[q]=d2[q]; }
                        t += 4;
                    }
                    float m1[4];
                    #pragma unroll
                    for (int q=0;q<4;q++) m1[q]=d_mul[(d1[q]&0x1FFFF)*Hh+lane];
                    #pragma unroll
                    for (int q=0;q<4;q++) PROC1(d0[q], m0[q]);
                    #pragma unroll
                    for (int q=0;q<4;q++) PROC1(d1[q], m1[q]);
                }
                for (; t<winE; t++){
                    int p = prow[t];
                    float mv = d_mul[(p&0x1FFFF)*Hh+lane];
                    PROC1(p, mv);
                }
                sCw[jcur*Hh+lane] += accv;     // flush final run
            }
            __syncwarp();

            // ---- phase B: z = C@W3 + af*W3[32] + b3 ; moments ; sparse z store ----
            unsigned rem = mM;
            while (rem){
                int b = __ffs(rem)-1; rem &= rem-1;
                const ulonglong2* Cj = (const ulonglong2*)(sCw + b*Hh);
                unsigned long long a0=0ull, a1=0ull;
                #pragma unroll
                for (int q=0;q<4;q++){
                    ulonglong2 cA = Cj[q];
                    ulonglong2 cB = Cj[q+4];
                    fma2(a0, cA.x, sW[(2*q)*32+lane]);     fma2(a0, cA.y, sW[(2*q+1)*32+lane]);
                    fma2(a1, cB.x, sW[(2*q+8)*32+lane]);   fma2(a1, cB.y, sW[(2*q+9)*32+lane]);
                }
                float acc = bb + upk_sum(a0) + upk_sum(a1) + (((mA>>b)&1u) ? w3last : 0.f);
                s1 += acc; s2 += acc*acc;
                if ((mN>>b)&1u) d_z[(size_t)(ij0+b)*Hh + lane] = acc;
            }
        }
    }
    sr1[w][lane]=s1; sr2[w][lane]=s2; if (lane==0) src[w]=c0;
    __syncthreads();
    if (w==0){
        float a=0.f, b=0.f;
        #pragma unroll
        for (int r=0;r<8;r++){ a+=sr1[r][lane]; b+=sr2[r][lane]; }
        atomicAdd(&d_S1[lane], a);
        atomicAdd(&d_S2[lane], b);
        if (lane==0){ int cc=0; for (int r=0;r<8;r++) cc+=src[r]; atomicAdd(&d_cntM, cc); }
    }
    if (tid==0) d_cnt[i]=0;                    // reset for replay
}

// ================= output =================
__global__ void k_pos(const int* __restrict__ pos, const float* __restrict__ linW,
                      const float* __restrict__ linb, float* __restrict__ out) {
    int w = threadIdx.x>>5, lane = threadIdx.x&31;
    int p = blockIdx.x*8 + w;
    float cnt = (float)d_cntM;
    float mean = d_S1[lane]/cnt;
    float inv  = rsqrtf(d_S2[lane]/cnt - mean*mean + 1e-5f);
    int p0 = pos[2*p], p1 = pos[2*p+1];
    float acc = d_h[p0*Hh+lane]*d_h[p1*Hh+lane]*linW[Hh+lane];
    if (d_maskb[p0*Nn+p1]) {
        float z1 = d_z[((size_t)p0*Nn+p1)*Hh+lane];
        float z2 = d_z[((size_t)p1*Nn+p0)*Hh+lane];
        acc += fmaxf((z1-mean)*inv,0.f)*fmaxf((z2-mean)*inv,0.f)*linW[lane];
    }
    for (int o=16;o;o>>=1) acc += __shfl_down_sync(0xffffffffu, acc, o);
    if (lane==0) out[p] = acc + linb[0];
}

// ================= launch =================
extern "C" void kernel_launch(void* const* d_in, const int* in_sizes, int n_in,
                              void* d_out, int out_size) {
    const int*   x    = (const int*)  d_in[0];
    const int*   ei   = (const int*)  d_in[1];
    const int*   pos  = (const int*)  d_in[2];
    const float* emb  = (const float*)d_in[3];
    const float* gcnW = (const float*)d_in[4];
    const float* gcnb = (const float*)d_in[5];
    const float* W1   = (const float*)d_in[6];
    const float* b1   = (const float*)d_in[7];
    const float* W2   = (const float*)d_in[8];
    const float* b2   = (const float*)d_in[9];
    const float* W3   = (const float*)d_in[10];
    const float* b3   = (const float*)d_in[11];
    const float* linW = (const float*)d_in[12];
    const float* linb = (const float*)d_in[13];
    float* out = (float*)d_out;

    k_sf     <<<96, 256>>>(ei, pos);
    k_build  <<<Nn, 256>>>();
    k_hw0    <<<96, 256>>>(x, emb, gcnW);
    k_agg<0> <<<NAGG,256>>>(gcnb);
    k_hw1    <<<96, 256>>>(gcnW);
    k_agg<1> <<<NAGG,256>>>(gcnb);
    k_norm1  <<<96, 256>>>();
    k_mlp    <<<Nn*STR/32,256>>>(W1,b1,W2,b2);
    k_z      <<<Nn, 256>>>(W3,b3);
    k_pos    <<<Pp/8,256>>>(pos, linW, linb, out);
}

// round 13
// speedup vs baseline: 1.2131x; 1.0031x over previous
#include <cuda_runtime.h>

#define Nn 768
#define Hh 32
#define Ee 24576
#define Pp 4096
#define NW 24              // 768/32 bitmask words per row
#define STR 96             // fixed CSR stride per row
#define BUD 6144           // per-row pair budget
#define NAGG 384

// ---------------- scratch ----------------
__device__ unsigned d_abits[Nn*NW];     // zeroed by k_z after last read
__device__ unsigned d_nbits[Nn*NW];     // zeroed by k_z after last read
__device__ unsigned char d_maskb[Nn*Nn];
__device__ float d_dinv[Nn];
__device__ float d_h [Nn*Hh];
__device__ float d_hT[Nn*Hh];
__device__ float d_hP[Nn*Hh];
__device__ int   d_cnt [Nn];            // zeroed by k_z
__device__ int   d_col[Nn*STR];
__device__ int   d_ijstart[Nn*Nn];      // local (within-row) pair-segment starts
__device__ int   d_ijend  [Nn*Nn];
__device__ int   d_pair1[Nn*BUD];       // f_glob | e_local<<17 | j_local<<24
__device__ float d_xe [Nn*STR*Hh];
__device__ float d_mul[Nn*STR*Hh];
__device__ float d_z  [(size_t)Nn*Nn*Hh];
__device__ float d_p1[NAGG*Hh], d_p2[NAGG*Hh];
__device__ float d_S1[Hh], d_S2[Hh];    // zeroed by k_sf
__device__ int   d_cntM;                // zeroed by k_sf

// ---------------- f32x2 helpers ----------------
__device__ __forceinline__ void fma2(unsigned long long& d, unsigned long long a, unsigned long long b){
    asm("fma.rn.f32x2 %0, %1, %2, %0;" : "+l"(d) : "l"(a), "l"(b));
}
__device__ __forceinline__ unsigned long long pk2(float lo, float hi){
    unsigned long long r; asm("mov.b64 %0,{%1,%2};" : "=l"(r) : "f"(lo), "f"(hi)); return r;
}
__device__ __forceinline__ float upk_sum(unsigned long long v){
    float lo, hi; asm("mov.b64 {%0,%1},%2;" : "=f"(lo), "=f"(hi) : "l"(v)); return lo+hi;
}

// ================= setup: scatter bits + fixed-stride CSR + zero stats =================
__global__ void k_sf(const int* __restrict__ ei, const int* __restrict__ pos) {
    int t = blockIdx.x*256 + threadIdx.x;
    if (t < Hh){ d_S1[t]=0.f; d_S2[t]=0.f; }
    if (t == Hh) d_cntM = 0;
    int u = ei[t], v = ei[Ee+t];
    atomicOr(&d_abits[u*NW+(v>>5)], 1u<<(v&31));
    int slot = atomicAdd(&d_cnt[u], 1);
    d_col[u*STR+slot] = v;
    if (t < Pp){
        int a=pos[2*t], b=pos[2*t+1];
        atomicOr(&d_nbits[a*NW+(b>>5)], 1u<<(b&31));
        atomicOr(&d_nbits[b*NW+(a>>5)], 1u<<(a&31));
    }
}

// ================= per-row pair build (768 blocks, two-pass, per-j buckets) =================
__global__ void __launch_bounds__(256) k_build() {
    __shared__ int scnt[Nn];
    __shared__ int scur[Nn];
    __shared__ int wsum[8];
    int tid = threadIdx.x, w = tid>>5, lane = tid&31;
    int i = blockIdx.x;
    for (int t=tid; t<Nn; t+=256) scnt[t]=0;
    __syncthreads();
    int es = i*STR, deg = d_cnt[i];
    for (int e=w; e<deg; e+=8){
        int k = d_col[es+e];
        int fk = k*STR, dk = d_cnt[k];
        for (int f=lane; f<dk; f+=32) atomicAdd(&scnt[d_col[fk+f]], 1);
    }
    __syncthreads();
    int lo = tid*3;
    int c0=scnt[lo], c1=scnt[lo+1], c2=scnt[lo+2];
    int s = c0+c1+c2, sc = s;
    #pragma unroll
    for (int o=1;o<32;o<<=1){ int t2=__shfl_up_sync(0xffffffffu,sc,o); if (lane>=o) sc+=t2; }
    if (lane==31) wsum[w]=sc;
    __syncthreads();
    if (w==0){
        int v = (lane<8) ? wsum[lane] : 0;
        int p = v;
        #pragma unroll
        for (int o=1;o<8;o<<=1){ int t2=__shfl_up_sync(0xffffffffu,p,o); if (lane>=o) p+=t2; }
        if (lane<8) wsum[lane]=p-v;
    }
    __syncthreads();
    int b0 = wsum[w] + sc - s;
    scur[lo]=b0; scur[lo+1]=b0+c0; scur[lo+2]=b0+c0+c1;
    d_ijstart[i*Nn+lo]  =b0;        d_ijend[i*Nn+lo]  =b0+c0;
    d_ijstart[i*Nn+lo+1]=b0+c0;     d_ijend[i*Nn+lo+1]=b0+c0+c1;
    d_ijstart[i*Nn+lo+2]=b0+c0+c1;  d_ijend[i*Nn+lo+2]=b0+c0+c1+c2;
    __syncthreads();
    int* prow = d_pair1 + i*BUD;
    for (int e=w; e<deg; e+=8){
        int k = d_col[es+e];
        int fk = k*STR, dk = d_cnt[k];
        for (int f=lane; f<dk; f+=32){
            int j = d_col[fk+f];
            int slot = atomicAdd(&scur[j], 1);
            prow[slot] = (fk+f) | (e<<17) | ((j&31)<<24);
        }
    }
}

// ================= GCN =================
// embed + dinv + hT = dinv * (emb[x] @ W0)
__global__ void k_hw0(const int* __restrict__ x, const float* __restrict__ emb,
                      const float* __restrict__ gcnW) {
    int w = threadIdx.x>>5, lane = threadIdx.x&31;
    int r = blockIdx.x*8 + w;
    int s = (lane<NW) ? __popc(d_abits[r*NW+lane]) : 0;
    #pragma unroll
    for (int o=16;o;o>>=1) s += __shfl_xor_sync(0xffffffffu, s, o);
    float dv = rsqrtf((float)s + 1.0f);
    if (lane==0) d_dinv[r] = dv;
    float hv = emb[x[r]*Hh+lane];
    float acc = 0.f;
    #pragma unroll
    for (int k=0;k<32;k++) acc += __shfl_sync(0xffffffffu,hv,k) * gcnW[k*Hh+lane];
    d_hT[r*Hh+lane] = dv*acc;
}

// agg: 384 blocks, 2 rows/block, warp = quarter-row (verified −2µs in R11/R12)
template<int L>
__global__ void k_agg(const float* __restrict__ gcnb) {
    __shared__ float sAg[8][32];
    __shared__ float red1[2][32], red2[2][32];
    int w = threadIdx.x>>5, lane = threadIdx.x&31;
    int r = blockIdx.x*2 + (w>>2);
    int quarter = w&3;
    float aggv = 0.f;
    #pragma unroll 1
    for (int wd=quarter*6; wd<quarter*6+6; wd++){
        unsigned m = d_abits[r*NW+wd];
        int jb = wd*32;
        while (m){ int b=__ffs(m)-1; m&=m-1; aggv += d_hT[(jb+b)*Hh+lane]; }
    }
    sAg[w][lane]=aggv;
    __syncthreads();
    if (quarter==0){
        float tot = sAg[w][lane]+sAg[w+1][lane]+sAg[w+2][lane]+sAg[w+3][lane];
        float v = d_dinv[r]*(tot + d_hT[r*Hh+lane]) + gcnb[L*Hh+lane];
        d_hP[r*Hh+lane]=v;
        red1[w>>2][lane]=v; red2[w>>2][lane]=v*v;
    }
    __syncthreads();
    if (w==0){
        float s1=red1[0][lane]+red1[1][lane];
        float s2=red2[0][lane]+red2[1][lane];
        d_p1[blockIdx.x*32+lane]=s1; d_p2[blockIdx.x*32+lane]=s2;
    }
}

__global__ void k_hw1(const float* __restrict__ gcnW) {
    int w = threadIdx.x>>5, lane = threadIdx.x&31;
    int r = blockIdx.x*8 + w;
    float s1=0.f, s2=0.f;
    #pragma unroll 4
    for (int b=0;b<NAGG;b++){ s1+=d_p1[b*32+lane]; s2+=d_p2[b*32+lane]; }
    float mean = s1/(float)Nn;
    float inv  = rsqrtf(s2/(float)Nn - mean*mean + 1e-5f);
    float hv = fmaxf((d_hP[r*Hh+lane]-mean)*inv, 0.f);
    float acc = 0.f;
    #pragma unroll
    for (int k=0;k<32;k++) acc += __shfl_sync(0xffffffffu,hv,k) * gcnW[Hh*Hh + k*Hh+lane];
    d_hT[r*Hh+lane] = d_dinv[r]*acc;
}

__global__ void k_norm1() {
    int w = threadIdx.x>>5, lane = threadIdx.x&31;
    int r = blockIdx.x*8 + w;
    float s1=0.f, s2=0.f;
    #pragma unroll 4
    for (int b=0;b<NAGG;b++){ s1+=d_p1[b*32+lane]; s2+=d_p2[b*32+lane]; }
    float mean = s1/(float)Nn;
    float inv  = rsqrtf(s2/(float)Nn - mean*mean + 1e-5f);
    d_h[r*Hh+lane] = fmaxf((d_hP[r*Hh+lane]-mean)*inv, 0.f);
}

// ================= edge MLPs: 4 edges per warp =================
__global__ void k_mlp(const float* __restrict__ W1, const float* __restrict__ b1,
                      const float* __restrict__ W2, const float* __restrict__ b2) {
    int w = threadIdx.x>>5, lane = threadIdx.x&31;
    int wid = blockIdx.x*8 + w;
    int s0 = wid*4;
    int u = s0/STR, idx0 = s0 - u*STR;
    int deg = d_cnt[u];
    if (idx0 >= deg) return;
    int nv = min(deg - idx0, 4);
    float hu = d_h[u*Hh+lane];
    float hv[4], x1[4], x2[4];
    #pragma unroll
    for (int q=0;q<4;q++){
        int v = (q<nv) ? d_col[s0+q] : d_col[s0];
        hv[q] = d_h[v*Hh+lane];
        x1[q] = b1[lane]; x2[q] = b2[lane];
    }
    #pragma unroll 4
    for (int k=0;k<32;k++){
        float w1a=W1[k*Hh+lane], w1b=W1[(k+32)*Hh+lane];
        float w2a=W2[k*Hh+lane], w2b=W2[(k+32)*Hh+lane];
        float a = __shfl_sync(0xffffffffu,hu,k);
        #pragma unroll
        for (int q=0;q<4;q++){
            float b = __shfl_sync(0xffffffffu,hv[q],k);
            x1[q] += a*w1a + b*w1b;
            x2[q] += a*w2a + b*w2b;
        }
    }
    #pragma unroll
    for (int q=0;q<4;q++){
        if (q<nv){
            d_xe [(s0+q)*Hh+lane]=fmaxf(x1[q],0.f);
            d_mul[(s0+q)*Hh+lane]=fmaxf(x2[q],0.f);
        }
    }
}

// ================= hot kernel: block = row; xe staged; plain RMW phase A (R9) =================
__global__ void __launch_bounds__(256,4) k_z(const float* __restrict__ W3,
                                             const float* __restrict__ b3v) {
    __shared__ unsigned long long sW[512];
    __shared__ float sxe[STR*Hh];
    __shared__ float sC[8][1024];
    __shared__ float sr1[8][32], sr2[8][32];
    __shared__ int src[8];
    int tid = threadIdx.x, w = tid>>5, lane = tid&31;
    int i = blockIdx.x;

    #pragma unroll
    for (int f=tid; f<512; f+=256){
        int t = f>>5, ln = f&31;
        sW[f] = pk2(W3[(2*t)*Hh+ln], W3[(2*t+1)*Hh+ln]);
    }
    int deg = d_cnt[i];
    {
        const float4* src4 = (const float4*)(d_xe + i*STR*Hh);
        float4* dst4 = (float4*)sxe;
        for (int t=tid; t<deg*8; t+=256) dst4[t]=src4[t];
    }
    __syncthreads();

    float w3last = W3[32*Hh+lane];
    float bb = b3v[lane];
    float s1=0.f, s2=0.f; int c0=0;
    float* sCw = sC[w];
    const int* prow = d_pair1 + i*BUD;

    #pragma unroll 1
    for (int win=w; win<NW; win+=8){
        int ij0 = i*Nn + win*32;
        int start = d_ijstart[ij0+lane];
        int end   = d_ijend  [ij0+lane];
        unsigned mA = d_abits[i*NW + win];
        unsigned mN = d_nbits[i*NW + win];
        unsigned hasP = __ballot_sync(0xffffffffu, end>start);
        unsigned mM = mA | hasP;
        d_maskb[ij0+lane] = (unsigned char)((mM>>lane)&1u);
        c0 += __popc(mM);
        if (lane==0){ d_abits[i*NW+win]=0u; d_nbits[i*NW+win]=0u; }  // reset for replay

        if (mM){
            {
                float4 z4 = make_float4(0.f,0.f,0.f,0.f);
                float4* p4 = (float4*)sCw;
                #pragma unroll
                for (int t=lane; t<256; t+=32) p4[t]=z4;
            }
            __syncwarp();

            // ---- phase A: flat stream; depth-2 value pipeline; straight-line smem RMW ----
            int winS = __shfl_sync(0xffffffffu, start, 0);
            int winE = __shfl_sync(0xffffffffu, end, 31);
            int t = winS;
            if (winE - winS >= 8){
                int d0[4], d1[4]; float m0[4];
                #pragma unroll
                for (int q=0;q<4;q++) d0[q]=prow[t+q];
                #pragma unroll
                for (int q=0;q<4;q++) d1[q]=prow[t+4+q];
                #pragma unroll
                for (int q=0;q<4;q++) m0[q]=d_mul[(d0[q]&0x1FFFF)*Hh+lane];
                t += 8;
                while (t+4 <= winE){
                    int d2[4];
                    #pragma unroll
                    for (int q=0;q<4;q++) d2[q]=prow[t+q];
                    float m1[4];
                    #pragma unroll
                    for (int q=0;q<4;q++) m1[q]=d_mul[(d1[q]&0x1FFFF)*Hh+lane];
                    #pragma unroll
                    for (int q=0;q<4;q++)
                        sCw[(d0[q]>>24)*Hh+lane] += sxe[((d0[q]>>17)&127)*Hh+lane]*m0[q];
                    #pragma unroll
                    for (int q=0;q<4;q++){ d0[q]=d1[q]; m0[q]=m1[q]; d1[q]=d2[q]; }
                    t += 4;
                }
                float m1[4];
                #pragma unroll
                for (int q=0;q<4;q++) m1[q]=d_mul[(d1[q]&0x1FFFF)*Hh+lane];
                #pragma unroll
                for (int q=0;q<4;q++)
                    sCw[(d0[q]>>24)*Hh+lane] += sxe[((d0[q]>>17)&127)*Hh+lane]*m0[q];
                #pragma unroll
                for (int q=0;q<4;q++)
                    sCw[(d1[q]>>24)*Hh+lane] += sxe[((d1[q]>>17)&127)*Hh+lane]*m1[q];
            }
            for (; t<winE; t++){
                int p = prow[t];
                sCw[(p>>24)*Hh+lane] += sxe[((p>>17)&127)*Hh+lane]*d_mul[(p&0x1FFFF)*Hh+lane];
            }
            __syncwarp();

            // ---- phase B: z = C@W3 + af*W3[32] + b3 ; moments ; sparse z store ----
            unsigned rem = mM;
            while (rem){
                int b = __ffs(rem)-1; rem &= rem-1;
                const ulonglong2* Cj = (const ulonglong2*)(sCw + b*Hh);
                unsigned long long a0=0ull, a1=0ull;
                #pragma unroll
                for (int q=0;q<4;q++){
                    ulonglong2 cA = Cj[q];
                    ulonglong2 cB = Cj[q+4];
                    fma2(a0, cA.x, sW[(2*q)*32+lane]);     fma2(a0, cA.y, sW[(2*q+1)*32+lane]);
                    fma2(a1, cB.x, sW[(2*q+8)*32+lane]);   fma2(a1, cB.y, sW[(2*q+9)*32+lane]);
                }
                float acc = bb + upk_sum(a0) + upk_sum(a1) + (((mA>>b)&1u) ? w3last : 0.f);
                s1 += acc; s2 += acc*acc;
                if ((mN>>b)&1u) d_z[(size_t)(ij0+b)*Hh + lane] = acc;
            }
        }
    }
    sr1[w][lane]=s1; sr2[w][lane]=s2; if (lane==0) src[w]=c0;
    __syncthreads();
    if (w==0){
        float a=0.f, b=0.f;
        #pragma unroll
        for (int r=0;r<8;r++){ a+=sr1[r][lane]; b+=sr2[r][lane]; }
        atomicAdd(&d_S1[lane], a);
        atomicAdd(&d_S2[lane], b);
        if (lane==0){ int cc=0; for (int r=0;r<8;r++) cc+=src[r]; atomicAdd(&d_cntM, cc); }
    }
    if (tid==0) d_cnt[i]=0;                    // reset for replay
}

// ================= output =================
__global__ void k_pos(const int* __restrict__ pos, const float* __restrict__ linW,
                      const float* __restrict__ linb, float* __restrict__ out) {
    int w = threadIdx.x>>5, lane = threadIdx.x&31;
    int p = blockIdx.x*8 + w;
    float cnt = (float)d_cntM;
    float mean = d_S1[lane]/cnt;
    float inv  = rsqrtf(d_S2[lane]/cnt - mean*mean + 1e-5f);
    int p0 = pos[2*p], p1 = pos[2*p+1];
    float acc = d_h[p0*Hh+lane]*d_h[p1*Hh+lane]*linW[Hh+lane];
    if (d_maskb[p0*Nn+p1]) {
        float z1 = d_z[((size_t)p0*Nn+p1)*Hh+lane];
        float z2 = d_z[((size_t)p1*Nn+p0)*Hh+lane];
        acc += fmaxf((z1-mean)*inv,0.f)*fmaxf((z2-mean)*inv,0.f)*linW[lane];
    }
    for (int o=16;o;o>>=1) acc += __shfl_down_sync(0xffffffffu, acc, o);
    if (lane==0) out[p] = acc + linb[0];
}

// ================= launch =================
extern "C" void kernel_launch(void* const* d_in, const int* in_sizes, int n_in,
                              void* d_out, int out_size) {
    const int*   x    = (const int*)  d_in[0];
    const int*   ei   = (const int*)  d_in[1];
    const int*   pos  = (const int*)  d_in[2];
    const float* emb  = (const float*)d_in[3];
    const float* gcnW = (const float*)d_in[4];
    const float* gcnb = (const float*)d_in[5];
    const float* W1   = (const float*)d_in[6];
    const float* b1   = (const float*)d_in[7];
    const float* W2   = (const float*)d_in[8];
    const float* b2   = (const float*)d_in[9];
    const float* W3   = (const float*)d_in[10];
    const float* b3   = (const float*)d_in[11];
    const float* linW = (const float*)d_in[12];
    const float* linb = (const float*)d_in[13];
    float* out = (float*)d_out;

    k_sf     <<<96, 256>>>(ei, pos);
    k_build  <<<Nn, 256>>>();
    k_hw0    <<<96, 256>>>(x, emb, gcnW);
    k_agg<0> <<<NAGG,256>>>(gcnb);
    k_hw1    <<<96, 256>>>(gcnW);
    k_agg<1> <<<NAGG,256>>>(gcnb);
    k_norm1  <<<96, 256>>>();
    k_mlp    <<<Nn*STR/32,256>>>(W1,b1,W2,b2);
    k_z      <<<Nn, 256>>>(W3,b3);
    k_pos    <<<Pp/8,256>>>(pos, linW, linb, out);
}

// round 14
// speedup vs baseline: 1.4143x; 1.1658x over previous
#include <cuda_runtime.h>

#define Nn 768
#define Hh 32
#define Ee 24576
#define Pp 4096
#define NW 24              // 768/32 bitmask words per row
#define STR 96             // fixed CSR stride per row
#define BUD 6144           // per-row pair budget
#define NAGG 192

// ---------------- scratch ----------------
__device__ unsigned d_abits[Nn*NW];     // zeroed by k_z after last read
__device__ unsigned d_nbits[Nn*NW];     // zeroed by k_z after last read
__device__ unsigned char d_maskb[Nn*Nn];
__device__ float d_dinv[Nn];
__device__ float d_h [Nn*Hh];
__device__ float d_hT[Nn*Hh];
__device__ float d_hP[Nn*Hh];
__device__ int   d_cnt [Nn];            // zeroed by k_z
__device__ int   d_col[Nn*STR];
__device__ int   d_ijstart[Nn*Nn];      // local (within-row) pair-segment starts
__device__ int   d_ijend  [Nn*Nn];
__device__ int   d_pair1[Nn*BUD];       // f_glob | e_local<<17 | j_local<<24
__device__ float d_xe [Nn*STR*Hh];
__device__ float d_mul[Nn*STR*Hh];
__device__ float d_z  [(size_t)Nn*Nn*Hh];
__device__ float d_p1[NAGG*Hh], d_p2[NAGG*Hh];
__device__ float d_S1[Hh], d_S2[Hh];    // zeroed by k_sf
__device__ int   d_cntM;                // zeroed by k_sf

// ---------------- f32x2 helpers ----------------
__device__ __forceinline__ void fma2(unsigned long long& d, unsigned long long a, unsigned long long b){
    asm("fma.rn.f32x2 %0, %1, %2, %0;" : "+l"(d) : "l"(a), "l"(b));
}
__device__ __forceinline__ unsigned long long pk2(float lo, float hi){
    unsigned long long r; asm("mov.b64 %0,{%1,%2};" : "=l"(r) : "f"(lo), "f"(hi)); return r;
}
__device__ __forceinline__ float upk_sum(unsigned long long v){
    float lo, hi; asm("mov.b64 {%0,%1},%2;" : "=f"(lo), "=f"(hi) : "l"(v)); return lo+hi;
}

// ================= setup: scatter bits + fixed-stride CSR + zero stats =================
__global__ void k_sf(const int* __restrict__ ei, const int* __restrict__ pos) {
    int t = blockIdx.x*256 + threadIdx.x;
    if (t < Hh){ d_S1[t]=0.f; d_S2[t]=0.f; }
    if (t == Hh) d_cntM = 0;
    int u = ei[t], v = ei[Ee+t];
    atomicOr(&d_abits[u*NW+(v>>5)], 1u<<(v&31));
    int slot = atomicAdd(&d_cnt[u], 1);
    d_col[u*STR+slot] = v;
    if (t < Pp){
        int a=pos[2*t], b=pos[2*t+1];
        atomicOr(&d_nbits[a*NW+(b>>5)], 1u<<(b&31));
        atomicOr(&d_nbits[b*NW+(a>>5)], 1u<<(a&31));
    }
}

// ================= per-row pair build (768 blocks, two-pass, per-j buckets) =================
__global__ void __launch_bounds__(256) k_build() {
    __shared__ int scnt[Nn];
    __shared__ int scur[Nn];
    __shared__ int wsum[8];
    int tid = threadIdx.x, w = tid>>5, lane = tid&31;
    int i = blockIdx.x;
    for (int t=tid; t<Nn; t+=256) scnt[t]=0;
    __syncthreads();
    int es = i*STR, deg = d_cnt[i];
    for (int e=w; e<deg; e+=8){
        int k = d_col[es+e];
        int fk = k*STR, dk = d_cnt[k];
        for (int f=lane; f<dk; f+=32) atomicAdd(&scnt[d_col[fk+f]], 1);
    }
    __syncthreads();
    int lo = tid*3;
    int c0=scnt[lo], c1=scnt[lo+1], c2=scnt[lo+2];
    int s = c0+c1+c2, sc = s;
    #pragma unroll
    for (int o=1;o<32;o<<=1){ int t2=__shfl_up_sync(0xffffffffu,sc,o); if (lane>=o) sc+=t2; }
    if (lane==31) wsum[w]=sc;
    __syncthreads();
    if (w==0){
        int v = (lane<8) ? wsum[lane] : 0;
        int p = v;
        #pragma unroll
        for (int o=1;o<8;o<<=1){ int t2=__shfl_up_sync(0xffffffffu,p,o); if (lane>=o) p+=t2; }
        if (lane<8) wsum[lane]=p-v;
    }
    __syncthreads();
    int b0 = wsum[w] + sc - s;
    scur[lo]=b0; scur[lo+1]=b0+c0; scur[lo+2]=b0+c0+c1;
    d_ijstart[i*Nn+lo]  =b0;        d_ijend[i*Nn+lo]  =b0+c0;
    d_ijstart[i*Nn+lo+1]=b0+c0;     d_ijend[i*Nn+lo+1]=b0+c0+c1;
    d_ijstart[i*Nn+lo+2]=b0+c0+c1;  d_ijend[i*Nn+lo+2]=b0+c0+c1+c2;
    __syncthreads();
    int* prow = d_pair1 + i*BUD;
    for (int e=w; e<deg; e+=8){
        int k = d_col[es+e];
        int fk = k*STR, dk = d_cnt[k];
        for (int f=lane; f<dk; f+=32){
            int j = d_col[fk+f];
            int slot = atomicAdd(&scur[j], 1);
            prow[slot] = (fk+f) | (e<<17) | ((j&31)<<24);
        }
    }
}

// ================= GCN =================
// embed + dinv + hT = dinv * (emb[x] @ W0)
__global__ void k_hw0(const int* __restrict__ x, const float* __restrict__ emb,
                      const float* __restrict__ gcnW) {
    int w = threadIdx.x>>5, lane = threadIdx.x&31;
    int r = blockIdx.x*8 + w;
    int s = (lane<NW) ? __popc(d_abits[r*NW+lane]) : 0;
    #pragma unroll
    for (int o=16;o;o>>=1) s += __shfl_xor_sync(0xffffffffu, s, o);
    float dv = rsqrtf((float)s + 1.0f);
    if (lane==0) d_dinv[r] = dv;
    float hv = emb[x[r]*Hh+lane];
    float acc = 0.f;
    #pragma unroll
    for (int k=0;k<32;k++) acc += __shfl_sync(0xffffffffu,hv,k) * gcnW[k*Hh+lane];
    d_hT[r*Hh+lane] = dv*acc;
}

// agg: 192 blocks, 4 rows/block, warp = half-row (the 150.1µs configuration)
template<int L>
__global__ void k_agg(const float* __restrict__ gcnb) {
    __shared__ float sAg[8][32];
    __shared__ float red1[4][32], red2[4][32];
    int w = threadIdx.x>>5, lane = threadIdx.x&31;
    int r = blockIdx.x*4 + (w>>1);
    int half = w&1;
    float aggv = 0.f;
    #pragma unroll 1
    for (int wd=half*12; wd<half*12+12; wd++){
        unsigned m = d_abits[r*NW+wd];
        int jb = wd*32;
        while (m){ int b=__ffs(m)-1; m&=m-1; aggv += d_hT[(jb+b)*Hh+lane]; }
    }
    sAg[w][lane]=aggv;
    __syncthreads();
    if (half==0){
        float tot = sAg[w][lane] + sAg[w+1][lane];
        float v = d_dinv[r]*(tot + d_hT[r*Hh+lane]) + gcnb[L*Hh+lane];
        d_hP[r*Hh+lane]=v;
        red1[w>>1][lane]=v; red2[w>>1][lane]=v*v;
    }
    __syncthreads();
    if (w==0){
        float s1=0.f, s2=0.f;
        #pragma unroll
        for (int q=0;q<4;q++){ s1+=red1[q][lane]; s2+=red2[q][lane]; }
        d_p1[blockIdx.x*32+lane]=s1; d_p2[blockIdx.x*32+lane]=s2;
    }
}

__global__ void k_hw1(const float* __restrict__ gcnW) {
    int w = threadIdx.x>>5, lane = threadIdx.x&31;
    int r = blockIdx.x*8 + w;
    float s1=0.f, s2=0.f;
    #pragma unroll 4
    for (int b=0;b<NAGG;b++){ s1+=d_p1[b*32+lane]; s2+=d_p2[b*32+lane]; }
    float mean = s1/(float)Nn;
    float inv  = rsqrtf(s2/(float)Nn - mean*mean + 1e-5f);
    float hv = fmaxf((d_hP[r*Hh+lane]-mean)*inv, 0.f);
    float acc = 0.f;
    #pragma unroll
    for (int k=0;k<32;k++) acc += __shfl_sync(0xffffffffu,hv,k) * gcnW[Hh*Hh + k*Hh+lane];
    d_hT[r*Hh+lane] = d_dinv[r]*acc;
}

__global__ void k_norm1() {
    int w = threadIdx.x>>5, lane = threadIdx.x&31;
    int r = blockIdx.x*8 + w;
    float s1=0.f, s2=0.f;
    #pragma unroll 4
    for (int b=0;b<NAGG;b++){ s1+=d_p1[b*32+lane]; s2+=d_p2[b*32+lane]; }
    float mean = s1/(float)Nn;
    float inv  = rsqrtf(s2/(float)Nn - mean*mean + 1e-5f);
    d_h[r*Hh+lane] = fmaxf((d_hP[r*Hh+lane]-mean)*inv, 0.f);
}

// ================= edge MLPs: 4 edges per warp =================
__global__ void k_mlp(const float* __restrict__ W1, const float* __restrict__ b1,
                      const float* __restrict__ W2, const float* __restrict__ b2) {
    int w = threadIdx.x>>5, lane = threadIdx.x&31;
    int wid = blockIdx.x*8 + w;
    int s0 = wid*4;
    int u = s0/STR, idx0 = s0 - u*STR;
    int deg = d_cnt[u];
    if (idx0 >= deg) return;
    int nv = min(deg - idx0, 4);
    float hu = d_h[u*Hh+lane];
    float hv[4], x1[4], x2[4];
    #pragma unroll
    for (int q=0;q<4;q++){
        int v = (q<nv) ? d_col[s0+q] : d_col[s0];
        hv[q] = d_h[v*Hh+lane];
        x1[q] = b1[lane]; x2[q] = b2[lane];
    }
    #pragma unroll 4
    for (int k=0;k<32;k++){
        float w1a=W1[k*Hh+lane], w1b=W1[(k+32)*Hh+lane];
        float w2a=W2[k*Hh+lane], w2b=W2[(k+32)*Hh+lane];
        float a = __shfl_sync(0xffffffffu,hu,k);
        #pragma unroll
        for (int q=0;q<4;q++){
            float b = __shfl_sync(0xffffffffu,hv[q],k);
            x1[q] += a*w1a + b*w1b;
            x2[q] += a*w2a + b*w2b;
        }
    }
    #pragma unroll
    for (int q=0;q<4;q++){
        if (q<nv){
            d_xe [(s0+q)*Hh+lane]=fmaxf(x1[q],0.f);
            d_mul[(s0+q)*Hh+lane]=fmaxf(x2[q],0.f);
        }
    }
}

// prefix-overwrite accumulate: per-j buckets => pairs with equal j are contiguous;
// run carries the prefix of the current run; STS overwrites, final store = run total.
// branch-free (FSETP+FSEL+FADD), no LDS, no BSSY.
#define PROCP(dv, mv) { \
    int jj_ = (dv)>>24; \
    float val_ = sxe[(((dv)>>17)&127)*Hh+lane]*(mv); \
    run = val_ + ((jj_==jprev) ? run : 0.f); \
    sCw[jj_*Hh+lane] = run; \
    jprev = jj_; }

// ================= hot kernel: block = row; xe staged; prefix-overwrite phase A =================
__global__ void __launch_bounds__(256,4) k_z(const float* __restrict__ W3,
                                             const float* __restrict__ b3v) {
    __shared__ unsigned long long sW[512];
    __shared__ float sxe[STR*Hh];
    __shared__ float sC[8][1024];
    __shared__ float sr1[8][32], sr2[8][32];
    __shared__ int src[8];
    int tid = threadIdx.x, w = tid>>5, lane = tid&31;
    int i = blockIdx.x;

    #pragma unroll
    for (int f=tid; f<512; f+=256){
        int t = f>>5, ln = f&31;
        sW[f] = pk2(W3[(2*t)*Hh+ln], W3[(2*t+1)*Hh+ln]);
    }
    int deg = d_cnt[i];
    {
        const float4* src4 = (const float4*)(d_xe + i*STR*Hh);
        float4* dst4 = (float4*)sxe;
        for (int t=tid; t<deg*8; t+=256) dst4[t]=src4[t];
    }
    __syncthreads();

    float w3last = W3[32*Hh+lane];
    float bb = b3v[lane];
    float s1=0.f, s2=0.f; int c0=0;
    float* sCw = sC[w];
    const int* prow = d_pair1 + i*BUD;

    #pragma unroll 1
    for (int win=w; win<NW; win+=8){
        int ij0 = i*Nn + win*32;
        int start = d_ijstart[ij0+lane];
        int end   = d_ijend  [ij0+lane];
        unsigned mA = d_abits[i*NW + win];
        unsigned mN = d_nbits[i*NW + win];
        unsigned hasP = __ballot_sync(0xffffffffu, end>start);
        unsigned mM = mA | hasP;
        d_maskb[ij0+lane] = (unsigned char)((mM>>lane)&1u);
        c0 += __popc(mM);
        if (lane==0){ d_abits[i*NW+win]=0u; d_nbits[i*NW+win]=0u; }  // reset for replay

        if (mM){
            {
                float4 z4 = make_float4(0.f,0.f,0.f,0.f);
                float4* p4 = (float4*)sCw;
                #pragma unroll
                for (int t=lane; t<256; t+=32) p4[t]=z4;
            }
            __syncwarp();

            // ---- phase A: flat stream; depth-2 value pipeline; prefix-overwrite ----
            int winS = __shfl_sync(0xffffffffu, start, 0);
            int winE = __shfl_sync(0xffffffffu, end, 31);
            int jprev = -1;
            float run = 0.f;
            int t = winS;
            if (winE - winS >= 8){
                int d0[4], d1[4]; float m0[4];
                #pragma unroll
                for (int q=0;q<4;q++) d0[q]=prow[t+q];
                #pragma unroll
                for (int q=0;q<4;q++) d1[q]=prow[t+4+q];
                #pragma unroll
                for (int q=0;q<4;q++) m0[q]=d_mul[(d0[q]&0x1FFFF)*Hh+lane];
                t += 8;
                while (t+4 <= winE){
                    int d2[4];
                    #pragma unroll
                    for (int q=0;q<4;q++) d2[q]=prow[t+q];
                    float m1[4];
                    #pragma unroll
                    for (int q=0;q<4;q++) m1[q]=d_mul[(d1[q]&0x1FFFF)*Hh+lane];
                    #pragma unroll
                    for (int q=0;q<4;q++) PROCP(d0[q], m0[q]);
                    #pragma unroll
                    for (int q=0;q<4;q++){ d0[q]=d1[q]; m0[q]=m1[q]; d1[q]=d2[q]; }
                    t += 4;
                }
                float m1[4];
                #pragma unroll
                for (int q=0;q<4;q++) m1[q]=d_mul[(d1[q]&0x1FFFF)*Hh+lane];
                #pragma unroll
                for (int q=0;q<4;q++) PROCP(d0[q], m0[q]);
                #pragma unroll
                for (int q=0;q<4;q++) PROCP(d1[q], m1[q]);
            }
            for (; t<winE; t++){
                int p = prow[t];
                float mv = d_mul[(p&0x1FFFF)*Hh+lane];
                PROCP(p, mv);
            }
            __syncwarp();

            // ---- phase B: z = C@W3 + af*W3[32] + b3 ; moments ; sparse z store ----
            unsigned rem = mM;
            while (rem){
                int b = __ffs(rem)-1; rem &= rem-1;
                const ulonglong2* Cj = (const ulonglong2*)(sCw + b*Hh);
                unsigned long long a0=0ull, a1=0ull;
                #pragma unroll
                for (int q=0;q<4;q++){
                    ulonglong2 cA = Cj[q];
                    ulonglong2 cB = Cj[q+4];
                    fma2(a0, cA.x, sW[(2*q)*32+lane]);     fma2(a0, cA.y, sW[(2*q+1)*32+lane]);
                    fma2(a1, cB.x, sW[(2*q+8)*32+lane]);   fma2(a1, cB.y, sW[(2*q+9)*32+lane]);
                }
                float acc = bb + upk_sum(a0) + upk_sum(a1) + (((mA>>b)&1u) ? w3last : 0.f);
                s1 += acc; s2 += acc*acc;
                if ((mN>>b)&1u) d_z[(size_t)(ij0+b)*Hh + lane] = acc;
            }
        }
    }
    sr1[w][lane]=s1; sr2[w][lane]=s2; if (lane==0) src[w]=c0;
    __syncthreads();
    if (w==0){
        float a=0.f, b=0.f;
        #pragma unroll
        for (int r=0;r<8;r++){ a+=sr1[r][lane]; b+=sr2[r][lane]; }
        atomicAdd(&d_S1[lane], a);
        atomicAdd(&d_S2[lane], b);
        if (lane==0){ int cc=0; for (int r=0;r<8;r++) cc+=src[r]; atomicAdd(&d_cntM, cc); }
    }
    if (tid==0) d_cnt[i]=0;                    // reset for replay
}

// ================= output =================
__global__ void k_pos(const int* __restrict__ pos, const float* __restrict__ linW,
                      const float* __restrict__ linb, float* __restrict__ out) {
    int w = threadIdx.x>>5, lane = threadIdx.x&31;
    int p = blockIdx.x*8 + w;
    float cnt = (float)d_cntM;
    float mean = d_S1[lane]/cnt;
    float inv  = rsqrtf(d_S2[lane]/cnt - mean*mean + 1e-5f);
    int p0 = pos[2*p], p1 = pos[2*p+1];
    float acc = d_h[p0*Hh+lane]*d_h[p1*Hh+lane]*linW[Hh+lane];
    if (d_maskb[p0*Nn+p1]) {
        float z1 = d_z[((size_t)p0*Nn+p1)*Hh+lane];
        float z2 = d_z[((size_t)p1*Nn+p0)*Hh+lane];
        acc += fmaxf((z1-mean)*inv,0.f)*fmaxf((z2-mean)*inv,0.f)*linW[lane];
    }
    for (int o=16;o;o>>=1) acc += __shfl_down_sync(0xffffffffu, acc, o);
    if (lane==0) out[p] = acc + linb[0];
}

// ================= launch =================
extern "C" void kernel_launch(void* const* d_in, const int* in_sizes, int n_in,
                              void* d_out, int out_size) {
    const int*   x    = (const int*)  d_in[0];
    const int*   ei   = (const int*)  d_in[1];
    const int*   pos  = (const int*)  d_in[2];
    const float* emb  = (const float*)d_in[3];
    const float* gcnW = (const float*)d_in[4];
    const float* gcnb = (const float*)d_in[5];
    const float* W1   = (const float*)d_in[6];
    const float* b1   = (const float*)d_in[7];
    const float* W2   = (const float*)d_in[8];
    const float* b2   = (const float*)d_in[9];
    const float* W3   = (const float*)d_in[10];
    const float* b3   = (const float*)d_in[11];
    const float* linW = (const float*)d_in[12];
    const float* linb = (const float*)d_in[13];
    float* out = (float*)d_out;

    k_sf     <<<96, 256>>>(ei, pos);
    k_build  <<<Nn, 256>>>();
    k_hw0    <<<96, 256>>>(x, emb, gcnW);
    k_agg<0> <<<NAGG,256>>>(gcnb);
    k_hw1    <<<96, 256>>>(gcnW);
    k_agg<1> <<<NAGG,256>>>(gcnb);
    k_norm1  <<<96, 256>>>();
    k_mlp    <<<Nn*STR/32,256>>>(W1,b1,W2,b2);
    k_z      <<<Nn, 256>>>(W3,b3);
    k_pos    <<<Pp/8,256>>>(pos, linW, linb, out);
}

// round 15
// speedup vs baseline: 1.4781x; 1.0451x over previous
#include <cuda_runtime.h>

#define Nn 768
#define Hh 32
#define Ee 24576
#define Pp 4096
#define NW 24              // 768/32 bitmask words per row
#define STR 96             // fixed CSR stride per row
#define BUD 6144           // per-row pair budget
#define NAGG 192

// ---------------- scratch ----------------
__device__ unsigned d_abits[Nn*NW];     // zeroed by k_z after last read
__device__ unsigned d_nbits[Nn*NW];     // zeroed by k_z after last read
__device__ unsigned char d_maskb[Nn*Nn];
__device__ float d_dinv[Nn];
__device__ float d_h [Nn*Hh];
__device__ float d_hT[Nn*Hh];
__device__ float d_hP[Nn*Hh];
__device__ int   d_cnt [Nn];            // dup CSR count; zeroed by k_z
__device__ int   d_cnt2[Nn];            // dedup CSR count; zeroed by k_z
__device__ int   d_col [Nn*STR];        // dup CSR (for pair build / MLP)
__device__ int   d_col2[Nn*STR];        // dedup CSR (for GCN aggregation)
__device__ int   d_ijstart[Nn*Nn];      // local (within-row) pair-segment starts
__device__ int   d_ijend  [Nn*Nn];
__device__ int   d_pair1[Nn*BUD];       // f_glob | e_local<<17 | j_local<<24
__device__ float d_xe [Nn*STR*Hh];
__device__ float d_mul[Nn*STR*Hh];
__device__ float d_z  [(size_t)Nn*Nn*Hh];
__device__ float d_p1[NAGG*Hh], d_p2[NAGG*Hh];
__device__ float d_S1[Hh], d_S2[Hh];    // zeroed by k_sf
__device__ int   d_cntM;                // zeroed by k_sf

// ---------------- f32x2 helpers ----------------
__device__ __forceinline__ void fma2(unsigned long long& d, unsigned long long a, unsigned long long b){
    asm("fma.rn.f32x2 %0, %1, %2, %0;" : "+l"(d) : "l"(a), "l"(b));
}
__device__ __forceinline__ unsigned long long pk2(float lo, float hi){
    unsigned long long r; asm("mov.b64 %0,{%1,%2};" : "=l"(r) : "f"(lo), "f"(hi)); return r;
}
__device__ __forceinline__ float upk_sum(unsigned long long v){
    float lo, hi; asm("mov.b64 {%0,%1},%2;" : "=f"(lo), "=f"(hi) : "l"(v)); return lo+hi;
}

// ================= setup: scatter bits + dup CSR + dedup CSR + zero stats =================
__global__ void k_sf(const int* __restrict__ ei, const int* __restrict__ pos) {
    int t = blockIdx.x*256 + threadIdx.x;
    if (t < Hh){ d_S1[t]=0.f; d_S2[t]=0.f; }
    if (t == Hh) d_cntM = 0;
    int u = ei[t], v = ei[Ee+t];
    unsigned bit = 1u<<(v&31);
    unsigned old = atomicOr(&d_abits[u*NW+(v>>5)], bit);
    int slot = atomicAdd(&d_cnt[u], 1);
    d_col[u*STR+slot] = v;
    if (!(old & bit)){                       // first occurrence -> dedup CSR
        int s2 = atomicAdd(&d_cnt2[u], 1);
        d_col2[u*STR+s2] = v;
    }
    if (t < Pp){
        int a=pos[2*t], b=pos[2*t+1];
        atomicOr(&d_nbits[a*NW+(b>>5)], 1u<<(b&31));
        atomicOr(&d_nbits[b*NW+(a>>5)], 1u<<(a&31));
    }
}

// ================= per-row pair build (768 blocks, two-pass, per-j buckets) =================
__global__ void __launch_bounds__(256) k_build() {
    __shared__ int scnt[Nn];
    __shared__ int scur[Nn];
    __shared__ int wsum[8];
    int tid = threadIdx.x, w = tid>>5, lane = tid&31;
    int i = blockIdx.x;
    for (int t=tid; t<Nn; t+=256) scnt[t]=0;
    __syncthreads();
    int es = i*STR, deg = d_cnt[i];
    for (int e=w; e<deg; e+=8){
        int k = d_col[es+e];
        int fk = k*STR, dk = d_cnt[k];
        for (int f=lane; f<dk; f+=32) atomicAdd(&scnt[d_col[fk+f]], 1);
    }
    __syncthreads();
    int lo = tid*3;
    int c0=scnt[lo], c1=scnt[lo+1], c2=scnt[lo+2];
    int s = c0+c1+c2, sc = s;
    #pragma unroll
    for (int o=1;o<32;o<<=1){ int t2=__shfl_up_sync(0xffffffffu,sc,o); if (lane>=o) sc+=t2; }
    if (lane==31) wsum[w]=sc;
    __syncthreads();
    if (w==0){
        int v = (lane<8) ? wsum[lane] : 0;
        int p = v;
        #pragma unroll
        for (int o=1;o<8;o<<=1){ int t2=__shfl_up_sync(0xffffffffu,p,o); if (lane>=o) p+=t2; }
        if (lane<8) wsum[lane]=p-v;
    }
    __syncthreads();
    int b0 = wsum[w] + sc - s;
    scur[lo]=b0; scur[lo+1]=b0+c0; scur[lo+2]=b0+c0+c1;
    d_ijstart[i*Nn+lo]  =b0;        d_ijend[i*Nn+lo]  =b0+c0;
    d_ijstart[i*Nn+lo+1]=b0+c0;     d_ijend[i*Nn+lo+1]=b0+c0+c1;
    d_ijstart[i*Nn+lo+2]=b0+c0+c1;  d_ijend[i*Nn+lo+2]=b0+c0+c1+c2;
    __syncthreads();
    int* prow = d_pair1 + i*BUD;
    for (int e=w; e<deg; e+=8){
        int k = d_col[es+e];
        int fk = k*STR, dk = d_cnt[k];
        for (int f=lane; f<dk; f+=32){
            int j = d_col[fk+f];
            int slot = atomicAdd(&scur[j], 1);
            prow[slot] = (fk+f) | (e<<17) | ((j&31)<<24);
        }
    }
}

// ================= GCN =================
// embed + dinv + hT = dinv * (emb[x] @ W0)
__global__ void k_hw0(const int* __restrict__ x, const float* __restrict__ emb,
                      const float* __restrict__ gcnW) {
    int w = threadIdx.x>>5, lane = threadIdx.x&31;
    int r = blockIdx.x*8 + w;
    float dv = rsqrtf((float)d_cnt2[r] + 1.0f);
    if (lane==0) d_dinv[r] = dv;
    float hv = emb[x[r]*Hh+lane];
    float acc = 0.f;
    #pragma unroll
    for (int k=0;k<32;k++) acc += __shfl_sync(0xffffffffu,hv,k) * gcnW[k*Hh+lane];
    d_hT[r*Hh+lane] = dv*acc;
}

// agg: 192 blocks, 4 rows/block, warp = half of dedup CSR (even/odd slots), unroll-4 gather
template<int L>
__global__ void k_agg(const float* __restrict__ gcnb) {
    __shared__ float sAg[8][32];
    __shared__ float red1[4][32], red2[4][32];
    int w = threadIdx.x>>5, lane = threadIdx.x&31;
    int r = blockIdx.x*4 + (w>>1);
    int half = w&1;
    int deg2 = d_cnt2[r];
    const int* cols = d_col2 + r*STR;
    float aggv = 0.f;
    int e = half;
    #pragma unroll 1
    for (; e+6 < deg2; e += 8){                 // 4 independent gathers per batch
        int c0=cols[e], c1=cols[e+2], c2=cols[e+4], c3=cols[e+6];
        float v0=d_hT[c0*Hh+lane];
        float v1=d_hT[c1*Hh+lane];
        float v2=d_hT[c2*Hh+lane];
        float v3=d_hT[c3*Hh+lane];
        aggv += (v0+v1)+(v2+v3);
    }
    #pragma unroll 1
    for (; e<deg2; e+=2) aggv += d_hT[cols[e]*Hh+lane];
    sAg[w][lane]=aggv;
    __syncthreads();
    if (half==0){
        float tot = sAg[w][lane] + sAg[w+1][lane];
        float v = d_dinv[r]*(tot + d_hT[r*Hh+lane]) + gcnb[L*Hh+lane];
        d_hP[r*Hh+lane]=v;
        red1[w>>1][lane]=v; red2[w>>1][lane]=v*v;
    }
    __syncthreads();
    if (w==0){
        float s1=0.f, s2=0.f;
        #pragma unroll
        for (int q=0;q<4;q++){ s1+=red1[q][lane]; s2+=red2[q][lane]; }
        d_p1[blockIdx.x*32+lane]=s1; d_p2[blockIdx.x*32+lane]=s2;
    }
}

__global__ void k_hw1(const float* __restrict__ gcnW) {
    int w = threadIdx.x>>5, lane = threadIdx.x&31;
    int r = blockIdx.x*8 + w;
    float s1=0.f, s2=0.f;
    #pragma unroll 4
    for (int b=0;b<NAGG;b++){ s1+=d_p1[b*32+lane]; s2+=d_p2[b*32+lane]; }
    float mean = s1/(float)Nn;
    float inv  = rsqrtf(s2/(float)Nn - mean*mean + 1e-5f);
    float hv = fmaxf((d_hP[r*Hh+lane]-mean)*inv, 0.f);
    float acc = 0.f;
    #pragma unroll
    for (int k=0;k<32;k++) acc += __shfl_sync(0xffffffffu,hv,k) * gcnW[Hh*Hh + k*Hh+lane];
    d_hT[r*Hh+lane] = d_dinv[r]*acc;
}

__global__ void k_norm1() {
    int w = threadIdx.x>>5, lane = threadIdx.x&31;
    int r = blockIdx.x*8 + w;
    float s1=0.f, s2=0.f;
    #pragma unroll 4
    for (int b=0;b<NAGG;b++){ s1+=d_p1[b*32+lane]; s2+=d_p2[b*32+lane]; }
    float mean = s1/(float)Nn;
    float inv  = rsqrtf(s2/(float)Nn - mean*mean + 1e-5f);
    d_h[r*Hh+lane] = fmaxf((d_hP[r*Hh+lane]-mean)*inv, 0.f);
}

// ================= edge MLPs: 4 edges per warp =================
__global__ void k_mlp(const float* __restrict__ W1, const float* __restrict__ b1,
                      const float* __restrict__ W2, const float* __restrict__ b2) {
    int w = threadIdx.x>>5, lane = threadIdx.x&31;
    int wid = blockIdx.x*8 + w;
    int s0 = wid*4;
    int u = s0/STR, idx0 = s0 - u*STR;
    int deg = d_cnt[u];
    if (idx0 >= deg) return;
    int nv = min(deg - idx0, 4);
    float hu = d_h[u*Hh+lane];
    float hv[4], x1[4], x2[4];
    #pragma unroll
    for (int q=0;q<4;q++){
        int v = (q<nv) ? d_col[s0+q] : d_col[s0];
        hv[q] = d_h[v*Hh+lane];
        x1[q] = b1[lane]; x2[q] = b2[lane];
    }
    #pragma unroll 4
    for (int k=0;k<32;k++){
        float w1a=W1[k*Hh+lane], w1b=W1[(k+32)*Hh+lane];
        float w2a=W2[k*Hh+lane], w2b=W2[(k+32)*Hh+lane];
        float a = __shfl_sync(0xffffffffu,hu,k);
        #pragma unroll
        for (int q=0;q<4;q++){
            float b = __shfl_sync(0xffffffffu,hv[q],k);
            x1[q] += a*w1a + b*w1b;
            x2[q] += a*w2a + b*w2b;
        }
    }
    #pragma unroll
    for (int q=0;q<4;q++){
        if (q<nv){
            d_xe [(s0+q)*Hh+lane]=fmaxf(x1[q],0.f);
            d_mul[(s0+q)*Hh+lane]=fmaxf(x2[q],0.f);
        }
    }
}

// prefix-overwrite accumulate (verified R14): per-j buckets => equal-j pairs contiguous.
#define PROCP(dv, mv) { \
    int jj_ = (dv)>>24; \
    float val_ = sxe[(((dv)>>17)&127)*Hh+lane]*(mv); \
    run = val_ + ((jj_==jprev) ? run : 0.f); \
    sCw[jj_*Hh+lane] = run; \
    jprev = jj_; }

// ================= hot kernel: block = row; xe staged; prefix-overwrite phase A =================
__global__ void __launch_bounds__(256,4) k_z(const float* __restrict__ W3,
                                             const float* __restrict__ b3v) {
    __shared__ unsigned long long sW[512];
    __shared__ float sxe[STR*Hh];
    __shared__ float sC[8][1024];
    __shared__ float sr1[8][32], sr2[8][32];
    __shared__ int src[8];
    int tid = threadIdx.x, w = tid>>5, lane = tid&31;
    int i = blockIdx.x;

    #pragma unroll
    for (int f=tid; f<512; f+=256){
        int t = f>>5, ln = f&31;
        sW[f] = pk2(W3[(2*t)*Hh+ln], W3[(2*t+1)*Hh+ln]);
    }
    int deg = d_cnt[i];
    {
        const float4* src4 = (const float4*)(d_xe + i*STR*Hh);
        float4* dst4 = (float4*)sxe;
        for (int t=tid; t<deg*8; t+=256) dst4[t]=src4[t];
    }
    __syncthreads();

    float w3last = W3[32*Hh+lane];
    float bb = b3v[lane];
    float s1=0.f, s2=0.f; int c0=0;
    float* sCw = sC[w];
    const int* prow = d_pair1 + i*BUD;

    #pragma unroll 1
    for (int win=w; win<NW; win+=8){
        int ij0 = i*Nn + win*32;
        int start = d_ijstart[ij0+lane];
        int end   = d_ijend  [ij0+lane];
        unsigned mA = d_abits[i*NW + win];
        unsigned mN = d_nbits[i*NW + win];
        unsigned hasP = __ballot_sync(0xffffffffu, end>start);
        unsigned mM = mA | hasP;
        d_maskb[ij0+lane] = (unsigned char)((mM>>lane)&1u);
        c0 += __popc(mM);
        if (lane==0){ d_abits[i*NW+win]=0u; d_nbits[i*NW+win]=0u; }  // reset for replay

        if (mM){
            {
                float4 z4 = make_float4(0.f,0.f,0.f,0.f);
                float4* p4 = (float4*)sCw;
                #pragma unroll
                for (int t=lane; t<256; t+=32) p4[t]=z4;
            }
            __syncwarp();

            // ---- phase A: flat stream; depth-2 value pipeline; prefix-overwrite ----
            int winS = __shfl_sync(0xffffffffu, start, 0);
            int winE = __shfl_sync(0xffffffffu, end, 31);
            int jprev = -1;
            float run = 0.f;
            int t = winS;
            if (winE - winS >= 8){
                int d0[4], d1[4]; float m0[4];
                #pragma unroll
                for (int q=0;q<4;q++) d0[q]=prow[t+q];
                #pragma unroll
                for (int q=0;q<4;q++) d1[q]=prow[t+4+q];
                #pragma unroll
                for (int q=0;q<4;q++) m0[q]=d_mul[(d0[q]&0x1FFFF)*Hh+lane];
                t += 8;
                while (t+4 <= winE){
                    int d2[4];
                    #pragma unroll
                    for (int q=0;q<4;q++) d2[q]=prow[t+q];
                    float m1[4];
                    #pragma unroll
                    for (int q=0;q<4;q++) m1[q]=d_mul[(d1[q]&0x1FFFF)*Hh+lane];
                    #pragma unroll
                    for (int q=0;q<4;q++) PROCP(d0[q], m0[q]);
                    #pragma unroll
                    for (int q=0;q<4;q++){ d0[q]=d1[q]; m0[q]=m1[q]; d1[q]=d2[q]; }
                    t += 4;
                }
                float m1[4];
                #pragma unroll
                for (int q=0;q<4;q++) m1[q]=d_mul[(d1[q]&0x1FFFF)*Hh+lane];
                #pragma unroll
                for (int q=0;q<4;q++) PROCP(d0[q], m0[q]);
                #pragma unroll
                for (int q=0;q<4;q++) PROCP(d1[q], m1[q]);
            }
            for (; t<winE; t++){
                int p = prow[t];
                float mv = d_mul[(p&0x1FFFF)*Hh+lane];
                PROCP(p, mv);
            }
            __syncwarp();

            // ---- phase B: z = C@W3 + af*W3[32] + b3 ; moments ; sparse z store ----
            unsigned rem = mM;
            while (rem){
                int b = __ffs(rem)-1; rem &= rem-1;
                const ulonglong2* Cj = (const ulonglong2*)(sCw + b*Hh);
                unsigned long long a0=0ull, a1=0ull;
                #pragma unroll
                for (int q=0;q<4;q++){
                    ulonglong2 cA = Cj[q];
                    ulonglong2 cB = Cj[q+4];
                    fma2(a0, cA.x, sW[(2*q)*32+lane]);     fma2(a0, cA.y, sW[(2*q+1)*32+lane]);
                    fma2(a1, cB.x, sW[(2*q+8)*32+lane]);   fma2(a1, cB.y, sW[(2*q+9)*32+lane]);
                }
                float acc = bb + upk_sum(a0) + upk_sum(a1) + (((mA>>b)&1u) ? w3last : 0.f);
                s1 += acc; s2 += acc*acc;
                if ((mN>>b)&1u) d_z[(size_t)(ij0+b)*Hh + lane] = acc;
            }
        }
    }
    sr1[w][lane]=s1; sr2[w][lane]=s2; if (lane==0) src[w]=c0;
    __syncthreads();
    if (w==0){
        float a=0.f, b=0.f;
        #pragma unroll
        for (int r=0;r<8;r++){ a+=sr1[r][lane]; b+=sr2[r][lane]; }
        atomicAdd(&d_S1[lane], a);
        atomicAdd(&d_S2[lane], b);
        if (lane==0){ int cc=0; for (int r=0;r<8;r++) cc+=src[r]; atomicAdd(&d_cntM, cc); }
    }
    if (tid==0){ d_cnt[i]=0; d_cnt2[i]=0; }    // reset for replay
}

// ================= output =================
__global__ void k_pos(const int* __restrict__ pos, const float* __restrict__ linW,
                      const float* __restrict__ linb, float* __restrict__ out) {
    int w = threadIdx.x>>5, lane = threadIdx.x&31;
    int p = blockIdx.x*8 + w;
    float cnt = (float)d_cntM;
    float mean = d_S1[lane]/cnt;
    float inv  = rsqrtf(d_S2[lane]/cnt - mean*mean + 1e-5f);
    int p0 = pos[2*p], p1 = pos[2*p+1];
    float acc = d_h[p0*Hh+lane]*d_h[p1*Hh+lane]*linW[Hh+lane];
    if (d_maskb[p0*Nn+p1]) {
        float z1 = d_z[((size_t)p0*Nn+p1)*Hh+lane];
        float z2 = d_z[((size_t)p1*Nn+p0)*Hh+lane];
        acc += fmaxf((z1-mean)*inv,0.f)*fmaxf((z2-mean)*inv,0.f)*linW[lane];
    }
    for (int o=16;o;o>>=1) acc += __shfl_down_sync(0xffffffffu, acc, o);
    if (lane==0) out[p] = acc + linb[0];
}

// ================= launch =================
extern "C" void kernel_launch(void* const* d_in, const int* in_sizes, int n_in,
                              void* d_out, int out_size) {
    const int*   x    = (const int*)  d_in[0];
    const int*   ei   = (const int*)  d_in[1];
    const int*   pos  = (const int*)  d_in[2];
    const float* emb  = (const float*)d_in[3];
    const float* gcnW = (const float*)d_in[4];
    const float* gcnb = (const float*)d_in[5];
    const float* W1   = (const float*)d_in[6];
    const float* b1   = (const float*)d_in[7];
    const float* W2   = (const float*)d_in[8];
    const float* b2   = (const float*)d_in[9];
    const float* W3   = (const float*)d_in[10];
    const float* b3   = (const float*)d_in[11];
    const float* linW = (const float*)d_in[12];
    const float* linb = (const float*)d_in[13];
    float* out = (float*)d_out;

    k_sf     <<<96, 256>>>(ei, pos);
    k_build  <<<Nn, 256>>>();
    k_hw0    <<<96, 256>>>(x, emb, gcnW);
    k_agg<0> <<<NAGG,256>>>(gcnb);
    k_hw1    <<<96, 256>>>(gcnW);
    k_agg<1> <<<NAGG,256>>>(gcnb);
    k_norm1  <<<96, 256>>>();
    k_mlp    <<<Nn*STR/32,256>>>(W1,b1,W2,b2);
    k_z      <<<Nn, 256>>>(W3,b3);
    k_pos    <<<Pp/8,256>>>(pos, linW, linb, out);
}